// round 2
// baseline (speedup 1.0000x reference)
#include <cuda_runtime.h>
#include <math.h>

// Problem constants
#define BB   32
#define NWAY 16
#define LQ   64
#define LD   256
#define DD   128
#define NEGV (-9999.0f)

typedef unsigned long long u64;

// Scratch (device globals: no allocations allowed)
__device__ float g_qA[BB * (DD/2) * LQ * 2];   // q normalized, layout [b][u=dd/2][q][2]  (1 MB)
__device__ float g_scores[BB * NWAY];          // MaxSim scores per (b,n)

// ---------------------------------------------------------------------------
// packed f32x2 FMA (Blackwell): c.lo += a.lo*b.lo ; c.hi += a.hi*b.hi
// ---------------------------------------------------------------------------
__device__ __forceinline__ void ffma2(u64 &c, u64 a, u64 b) {
    asm("fma.rn.f32x2 %0, %1, %2, %0;" : "+l"(c) : "l"(a), "l"(b));
}
__device__ __forceinline__ float2 u64_to_f2(u64 x) {
    float2 r;
    asm("mov.b64 {%0, %1}, %2;" : "=f"(r.x), "=f"(r.y) : "l"(x));
    return r;
}

// ---------------------------------------------------------------------------
// Kernel 1: normalize q rows, write transposed & dd-pair interleaved:
//   g_qA[((b*64 + (dd>>1))*64 + q)*2 + (dd&1)] = q_hat[b][q][dd]
// ---------------------------------------------------------------------------
__global__ void qnorm_kernel(const float* __restrict__ q) {
    int b    = blockIdx.x;
    int w    = threadIdx.x >> 5;
    int lane = threadIdx.x & 31;
    #pragma unroll
    for (int qrow = w; qrow < LQ; qrow += 8) {
        float4 v = *(const float4*)(q + ((size_t)(b * LQ + qrow)) * DD + lane * 4);
        float ss = v.x * v.x + v.y * v.y + v.z * v.z + v.w * v.w;
        #pragma unroll
        for (int o = 16; o; o >>= 1) ss += __shfl_xor_sync(0xFFFFFFFFu, ss, o);
        float rnq = 1.0f / fmaxf(sqrtf(ss), 1e-12f);
        float vals[4] = {v.x, v.y, v.z, v.w};
        #pragma unroll
        for (int j = 0; j < 4; j++) {
            int dd = lane * 4 + j;
            g_qA[(( (size_t)b * (DD/2) + (dd >> 1)) * LQ + qrow) * 2 + (dd & 1)] = vals[j] * rnq;
        }
    }
}

// ---------------------------------------------------------------------------
// Kernel 2: main. One CTA per (b, n). 256 threads.
// smem layout (dynamic):
//   As : [u=0..63][q=0..63] float2      32 KB   (q-hat, dd-pair interleaved)
//   Bs : [u=0..63] rows of 1 KB         64 KB   (d raw, 16B-unit XOR swizzle)
//        addr(u,k) = u*1024 + (((k>>1) ^ u) << 4) + ((k&1) << 3)
//   rn : float[128], msk : int[128], ws : float[8]
// ---------------------------------------------------------------------------
#define SMEM_AS   0
#define SMEM_BS   32768
#define SMEM_RN   (32768 + 65536)           // 98304
#define SMEM_MSK  (SMEM_RN + 512)           // 98816
#define SMEM_WS   (SMEM_MSK + 512)          // 99328
#define SMEM_TOTAL (SMEM_WS + 64)           // 99392

__global__ void __launch_bounds__(256, 2) colbert_main(
    const float* __restrict__ dreps, const int* __restrict__ dmask)
{
    extern __shared__ char smem[];
    float* rn  = (float*)(smem + SMEM_RN);
    int*   msk = (int*)  (smem + SMEM_MSK);
    float* ws  = (float*)(smem + SMEM_WS);

    const int bn   = blockIdx.x;        // b*16 + n
    const int b    = bn >> 4;
    const int t    = threadIdx.x;
    const int lane = t & 31;
    const int qtid = t >> 5;            // warp id = q group

    // ---- load A tile (contiguous copy, coalesced) ----
    {
        const float4* src = (const float4*)(g_qA + (size_t)b * (DD/2) * LQ * 2);
        float4* dst = (float4*)(smem + SMEM_AS);
        #pragma unroll
        for (int i = 0; i < 8; i++) dst[t + 256 * i] = src[t + 256 * i];
    }

    float m[8];
    #pragma unroll
    for (int qi = 0; qi < 8; qi++) m[qi] = -INFINITY;

    const float* dbase = dreps + (size_t)bn * LD * DD;
    const int*   mbase = dmask + bn * LD;

    for (int c = 0; c < 2; c++) {
        __syncthreads();   // Bs free to overwrite; As complete (first iter)

        // ---- load B chunk with swizzle: k in [c*128, c*128+128) ----
        const float4* gsrc = (const float4*)(dbase + (size_t)c * 128 * DD);
        #pragma unroll
        for (int i = 0; i < 16; i++) {
            int f  = t + 256 * i;       // warp covers one k row (32 x 16B units)
            int kl = f >> 5;            // local k
            int u4 = f & 31;            // 16B unit along dd
            float4 v = gsrc[f];
            int u0 = 2 * u4, u1 = 2 * u4 + 1;
            int un0 = (kl >> 1) ^ u0;
            int un1 = (kl >> 1) ^ u1;
            int half = (kl & 1) << 3;
            *(float2*)(smem + SMEM_BS + u0 * 1024 + (un0 << 4) + half) = make_float2(v.x, v.y);
            *(float2*)(smem + SMEM_BS + u1 * 1024 + (un1 << 4) + half) = make_float2(v.z, v.w);
        }
        if (t < 128) msk[t] = mbase[c * 128 + t];
        __syncthreads();

        // ---- per-row inverse norms of d (from smem) ----
        if (t < 128) {
            float ss = 0.0f;
            int kun  = t >> 1;
            int half = (t & 1) << 3;
            #pragma unroll 8
            for (int u = 0; u < 64; u++) {
                float2 v = *(const float2*)(smem + SMEM_BS + u * 1024 + ((kun ^ u) << 4) + half);
                ss = fmaf(v.x, v.x, fmaf(v.y, v.y, ss));
            }
            rn[t] = 1.0f / fmaxf(sqrtf(ss), 1e-12f);
        }
        __syncthreads();

        // ---- GEMM: 8q x 4k micro-tile, f32x2 packed over dd pairs ----
        u64 acc[8][4];
        #pragma unroll
        for (int qi = 0; qi < 8; qi++)
            #pragma unroll
            for (int kk = 0; kk < 4; kk++) acc[qi][kk] = 0ull;

        #pragma unroll 2
        for (int u = 0; u < 64; u++) {
            u64 qp[8];
            #pragma unroll
            for (int g = 0; g < 4; g++) {
                ulonglong2 qq = *(const ulonglong2*)(smem + SMEM_AS + u * 512 + qtid * 64 + g * 16);
                qp[2 * g]     = qq.x;
                qp[2 * g + 1] = qq.y;
            }
            u64 dp[4];
            #pragma unroll
            for (int kk = 0; kk < 4; kk++) {
                int klocal = lane + 32 * kk;
                int un = (klocal >> 1) ^ u;
                dp[kk] = *(const u64*)(smem + SMEM_BS + u * 1024 + (un << 4) + ((klocal & 1) << 3));
            }
            #pragma unroll
            for (int qi = 0; qi < 8; qi++)
                #pragma unroll
                for (int kk = 0; kk < 4; kk++)
                    ffma2(acc[qi][kk], qp[qi], dp[kk]);
        }

        // ---- score: mask -> NEG, scale by 1/||d||, running row-max over k ----
        #pragma unroll
        for (int kk = 0; kk < 4; kk++) {
            int klocal = lane + 32 * kk;
            float r  = rn[klocal];
            bool  on = (msk[klocal] != 0);
            #pragma unroll
            for (int qi = 0; qi < 8; qi++) {
                float2 f = u64_to_f2(acc[qi][kk]);
                float s = on ? (f.x + f.y) * r : NEGV;
                m[qi] = fmaxf(m[qi], s);
            }
        }
    }

    // ---- reduce: max over lanes (k), sum over q ----
    float partial = 0.0f;
    #pragma unroll
    for (int qi = 0; qi < 8; qi++) {
        float v = m[qi];
        #pragma unroll
        for (int o = 16; o; o >>= 1) v = fmaxf(v, __shfl_xor_sync(0xFFFFFFFFu, v, o));
        partial += v;
    }
    if (lane == 0) ws[qtid] = partial;
    __syncthreads();
    if (t == 0) {
        float sc = 0.0f;
        #pragma unroll
        for (int w = 0; w < 8; w++) sc += ws[w];
        g_scores[bn] = sc;
    }
}

// ---------------------------------------------------------------------------
// Kernel 3: softmax over nway + KL(batchmean, log_target) -> scalar
// ---------------------------------------------------------------------------
__global__ void finalize_kernel(const float* __restrict__ labels, float* __restrict__ out) {
    int b = threadIdx.x;   // 32 threads, one batch row each
    float s[NWAY];
    float mx = -INFINITY;
    #pragma unroll
    for (int n = 0; n < NWAY; n++) {
        s[n] = g_scores[b * NWAY + n];
        mx = fmaxf(mx, s[n]);
    }
    float se = 0.0f;
    #pragma unroll
    for (int n = 0; n < NWAY; n++) se += expf(s[n] - mx);
    float lse = mx + logf(se);
    float loss = 0.0f;
    #pragma unroll
    for (int n = 0; n < NWAY; n++) {
        float lab = labels[b * NWAY + n];
        loss += expf(lab) * (lab - (s[n] - lse));
    }
    #pragma unroll
    for (int o = 16; o; o >>= 1) loss += __shfl_xor_sync(0xFFFFFFFFu, loss, o);
    if (b == 0) out[0] = loss / (float)BB;
}

// ---------------------------------------------------------------------------
extern "C" void kernel_launch(void* const* d_in, const int* in_sizes, int n_in,
                              void* d_out, int out_size) {
    (void)in_sizes; (void)n_in; (void)out_size;
    const float* q      = (const float*)d_in[0];
    const float* dreps  = (const float*)d_in[1];
    const int*   dmask  = (const int*)  d_in[2];
    const float* labels = (const float*)d_in[3];

    cudaFuncSetAttribute(colbert_main, cudaFuncAttributeMaxDynamicSharedMemorySize, SMEM_TOTAL);

    qnorm_kernel<<<BB, 256>>>(q);
    colbert_main<<<BB * NWAY, 256, SMEM_TOTAL>>>(dreps, dmask);
    finalize_kernel<<<1, 32>>>(labels, (float*)d_out);
}

// round 3
// speedup vs baseline: 1.0348x; 1.0348x over previous
#include <cuda_runtime.h>
#include <math.h>

// Problem constants
#define BB   32
#define NWAY 16
#define LQ   64
#define LD   256
#define DD   128
#define NEGV (-9999.0f)

typedef unsigned long long u64;

// Scratch (device globals: no allocations allowed)
// g_qA layout (floats): b*8192 + u*128 + (qi>>1)*32 + qg*4 + (qi&1)*2 + (dd&1)
//   where u = dd>>1, qg = q>>3, qi = q&7
__device__ float g_qA[BB * LQ * DD];
__device__ float g_scores[BB * NWAY];

// ---------------------------------------------------------------------------
// packed f32x2 FMA (Blackwell): c.lo += a.lo*b.lo ; c.hi += a.hi*b.hi
// ---------------------------------------------------------------------------
__device__ __forceinline__ void ffma2(u64 &c, u64 a, u64 b) {
    asm("fma.rn.f32x2 %0, %1, %2, %0;" : "+l"(c) : "l"(a), "l"(b));
}
__device__ __forceinline__ float2 u64_to_f2(u64 x) {
    float2 r;
    asm("mov.b64 {%0, %1}, %2;" : "=f"(r.x), "=f"(r.y) : "l"(x));
    return r;
}

// ---------------------------------------------------------------------------
// Kernel 1: normalize q rows, write in the GEMM A-tile layout.
// grid = BB*8 CTAs of 256 threads; each warp handles exactly one q row.
// ---------------------------------------------------------------------------
__global__ void qnorm_kernel(const float* __restrict__ q) {
    int b    = blockIdx.x >> 3;
    int rb   = blockIdx.x & 7;
    int w    = threadIdx.x >> 5;
    int lane = threadIdx.x & 31;
    int qrow = rb * 8 + w;

    float4 v = *(const float4*)(q + ((size_t)(b * LQ + qrow)) * DD + lane * 4);
    float ss = v.x * v.x + v.y * v.y + v.z * v.z + v.w * v.w;
    #pragma unroll
    for (int o = 16; o; o >>= 1) ss += __shfl_xor_sync(0xFFFFFFFFu, ss, o);
    float rnq = 1.0f / fmaxf(sqrtf(ss), 1e-12f);

    int qg = qrow >> 3, qi = qrow & 7;
    float* base = g_qA + (size_t)b * 8192 + (qi >> 1) * 32 + qg * 4 + (qi & 1) * 2;
    float vals[4] = {v.x, v.y, v.z, v.w};
    #pragma unroll
    for (int j = 0; j < 4; j++) {
        int dd = lane * 4 + j;
        int u  = dd >> 1;
        base[u * 128 + (dd & 1)] = vals[j] * rnq;
    }
}

// ---------------------------------------------------------------------------
// Kernel 2: main. One CTA per (b, n). 256 threads, 2 CTAs/SM.
// smem:
//   As : [u][qi>>1][qg][qi&1] float pairs   32 KB
//        byte(u,q,par) = u*512 + (qi>>1)*128 + qg*16 + (qi&1)*8 + par*4
//   Bs : [u] rows of 1 KB, 16B-unit XOR swizzle                 64 KB
//        byte(u,k) = u*1024 + (((k>>1)^u)&63)*16 + (k&1)*8
//   rn[128], msk[128], partial[512], ws[2]
// ---------------------------------------------------------------------------
#define SMEM_AS    0
#define SMEM_BS    32768
#define SMEM_RN    98304
#define SMEM_MSK   98816
#define SMEM_PART  99328
#define SMEM_WS    101376
#define SMEM_TOTAL 101440

__global__ void __launch_bounds__(256, 2) colbert_main(
    const float* __restrict__ dreps, const int* __restrict__ dmask)
{
    extern __shared__ char smem[];
    float* rn   = (float*)(smem + SMEM_RN);
    int*   msk  = (int*)  (smem + SMEM_MSK);
    float* part = (float*)(smem + SMEM_PART);
    float* ws   = (float*)(smem + SMEM_WS);

    const int bn   = blockIdx.x;        // b*16 + n
    const int b    = bn >> 4;
    const int t    = threadIdx.x;
    const int lane = t & 31;
    const int w    = t >> 5;            // warp id -> k block of 16
    const int qg   = lane >> 2;         // q group (8 q each)
    const int kg   = lane & 3;          // k group within warp (4 k each)

    // ---- load A tile (contiguous copy; g_qA already in target layout) ----
    {
        const float4* src = (const float4*)(g_qA + (size_t)b * 8192);
        float4* dst = (float4*)(smem + SMEM_AS);
        #pragma unroll
        for (int i = 0; i < 8; i++) dst[t + 256 * i] = src[t + 256 * i];
    }

    float m[8];
    #pragma unroll
    for (int qi = 0; qi < 8; qi++) m[qi] = -INFINITY;

    const float* dbase = dreps + (size_t)bn * LD * DD;
    const int*   mbase = dmask + bn * LD;

    for (int c = 0; c < 2; c++) {
        __syncthreads();   // Bs free to overwrite; As complete (first iter)

        // ---- load B chunk with swizzle: k in [c*128, c*128+128) ----
        const float4* gsrc = (const float4*)(dbase + (size_t)c * 128 * DD);
        #pragma unroll
        for (int i = 0; i < 16; i++) {
            int f  = t + 256 * i;
            int kl = f >> 5;            // local k
            int u4 = f & 31;            // 16B unit along dd
            float4 v = gsrc[f];
            int u0 = 2 * u4, u1 = 2 * u4 + 1;
            int un0 = ((kl >> 1) ^ u0) & 63;
            int un1 = ((kl >> 1) ^ u1) & 63;
            int half = (kl & 1) << 3;
            *(float2*)(smem + SMEM_BS + u0 * 1024 + (un0 << 4) + half) = make_float2(v.x, v.y);
            *(float2*)(smem + SMEM_BS + u1 * 1024 + (un1 << 4) + half) = make_float2(v.z, v.w);
        }
        if (t < 128) msk[t] = mbase[c * 128 + t];
        __syncthreads();

        // ---- per-row inverse norms of d (from smem) ----
        if (t < 128) {
            float ss = 0.0f;
            int kun  = t >> 1;
            int half = (t & 1) << 3;
            #pragma unroll 8
            for (int u = 0; u < 64; u++) {
                float2 v = *(const float2*)(smem + SMEM_BS + u * 1024 + (((kun ^ u) & 63) << 4) + half);
                ss = fmaf(v.x, v.x, fmaf(v.y, v.y, ss));
            }
            rn[t] = 1.0f / fmaxf(sqrtf(ss), 1e-12f);
        }
        __syncthreads();

        // ---- GEMM: 2D lane tile. Thread = (qg, kg): 8 q x 4 k ----
        u64 acc[8][4];
        #pragma unroll
        for (int qi = 0; qi < 8; qi++)
            #pragma unroll
            for (int kk = 0; kk < 4; kk++) acc[qi][kk] = 0ull;

        for (int u = 0; u < 64; u++) {
            u64 qp[8];
            #pragma unroll
            for (int g = 0; g < 4; g++) {
                ulonglong2 qq = *(const ulonglong2*)(smem + SMEM_AS + u * 512 + g * 128 + qg * 16);
                qp[2 * g]     = qq.x;
                qp[2 * g + 1] = qq.y;
            }
            u64 dp[4];
            #pragma unroll
            for (int jj = 0; jj < 2; jj++) {
                int unit = ((w * 8 + kg * 2 + jj) ^ u) & 63;
                ulonglong2 dd2 = *(const ulonglong2*)(smem + SMEM_BS + u * 1024 + (unit << 4));
                dp[2 * jj]     = dd2.x;
                dp[2 * jj + 1] = dd2.y;
            }
            #pragma unroll
            for (int qi = 0; qi < 8; qi++)
                #pragma unroll
                for (int kk = 0; kk < 4; kk++)
                    ffma2(acc[qi][kk], qp[qi], dp[kk]);
        }

        // ---- score: mask -> NEG, scale by 1/||d||, running row-max over k ----
        #pragma unroll
        for (int kk = 0; kk < 4; kk++) {
            int kic = w * 16 + kg * 4 + kk;
            float r  = rn[kic];
            bool  on = (msk[kic] != 0);
            #pragma unroll
            for (int qi = 0; qi < 8; qi++) {
                float2 f = u64_to_f2(acc[qi][kk]);
                float s = on ? (f.x + f.y) * r : NEGV;
                m[qi] = fmaxf(m[qi], s);
            }
        }
    }

    // ---- reduce: max over kg lanes, then over warps, then sum over q ----
    #pragma unroll
    for (int qi = 0; qi < 8; qi++) {
        float v = m[qi];
        v = fmaxf(v, __shfl_xor_sync(0xFFFFFFFFu, v, 1));
        v = fmaxf(v, __shfl_xor_sync(0xFFFFFFFFu, v, 2));
        m[qi] = v;
    }
    if (kg == 0) {
        #pragma unroll
        for (int qi = 0; qi < 8; qi++) part[w * 64 + qg * 8 + qi] = m[qi];
    }
    __syncthreads();
    if (t < 64) {
        float v = part[t];
        #pragma unroll
        for (int w2 = 1; w2 < 8; w2++) v = fmaxf(v, part[w2 * 64 + t]);
        // sum over q (64 values across 2 full warps)
        #pragma unroll
        for (int o = 16; o; o >>= 1) v += __shfl_xor_sync(0xFFFFFFFFu, v, o);
        if (lane == 0) ws[t >> 5] = v;
    }
    __syncthreads();
    if (t == 0) g_scores[bn] = ws[0] + ws[1];
}

// ---------------------------------------------------------------------------
// Kernel 3: softmax over nway + KL(batchmean, log_target) -> scalar
// ---------------------------------------------------------------------------
__global__ void finalize_kernel(const float* __restrict__ labels, float* __restrict__ out) {
    int b = threadIdx.x;   // 32 threads, one batch row each
    float s[NWAY];
    float mx = -INFINITY;
    #pragma unroll
    for (int n = 0; n < NWAY; n++) {
        s[n] = g_scores[b * NWAY + n];
        mx = fmaxf(mx, s[n]);
    }
    float se = 0.0f;
    #pragma unroll
    for (int n = 0; n < NWAY; n++) se += expf(s[n] - mx);
    float lse = mx + logf(se);
    float loss = 0.0f;
    #pragma unroll
    for (int n = 0; n < NWAY; n++) {
        float lab = labels[b * NWAY + n];
        loss += expf(lab) * (lab - (s[n] - lse));
    }
    #pragma unroll
    for (int o = 16; o; o >>= 1) loss += __shfl_xor_sync(0xFFFFFFFFu, loss, o);
    if (b == 0) out[0] = loss / (float)BB;
}

// ---------------------------------------------------------------------------
extern "C" void kernel_launch(void* const* d_in, const int* in_sizes, int n_in,
                              void* d_out, int out_size) {
    (void)in_sizes; (void)n_in; (void)out_size;
    const float* q      = (const float*)d_in[0];
    const float* dreps  = (const float*)d_in[1];
    const int*   dmask  = (const int*)  d_in[2];
    const float* labels = (const float*)d_in[3];

    cudaFuncSetAttribute(colbert_main, cudaFuncAttributeMaxDynamicSharedMemorySize, SMEM_TOTAL);

    qnorm_kernel<<<BB * 8, 256>>>(q);
    colbert_main<<<BB * NWAY, 256, SMEM_TOTAL>>>(dreps, dmask);
    finalize_kernel<<<1, 32>>>(labels, (float*)d_out);
}

// round 5
// speedup vs baseline: 1.9161x; 1.8517x over previous
#include <cuda_runtime.h>
#include <cuda_bf16.h>
#include <math.h>
#include <stdint.h>

#define BB   32
#define NWAY 16
#define LQ   64
#define LD   256
#define DD   128
#define NEGV (-9999.0f)

typedef unsigned long long u64;

__device__ float g_scores[BB * NWAY];
__device__ int   g_cnt;                 // zero-init; reset by last CTA each launch

// ---------------- smem layout (dynamic) ----------------
// Tiles: 256B rows (16 x 16B units), unit swizzle: u' = u ^ (row & 7)
#define S_MSK   0                       // 128 ints
#define S_PART  512                     // 8*64 floats = 2048
#define S_WS    2560                    // 2 floats
#define S_QHI   4096                    // 64 x 256B  = 16384
#define S_QLO   20480
#define S_DHI   36864                   // 128 x 256B = 32768
#define S_DLO   69632
#define S_TOTAL 102400

__device__ __forceinline__ uint32_t smem_u32(const void* p) {
    uint32_t a;
    asm("{ .reg .u64 t; cvta.to.shared.u64 t, %1; cvt.u32.u64 %0, t; }" : "=r"(a) : "l"(p));
    return a;
}

__device__ __forceinline__ void ldsm4(uint32_t* r, uint32_t addr) {
    asm volatile("ldmatrix.sync.aligned.m8n8.x4.shared.b16 {%0,%1,%2,%3}, [%4];"
                 : "=r"(r[0]), "=r"(r[1]), "=r"(r[2]), "=r"(r[3]) : "r"(addr));
}

__device__ __forceinline__ void mma_bf16(float* c, const uint32_t* a, uint32_t b0, uint32_t b1) {
    asm volatile(
        "mma.sync.aligned.m16n8k16.row.col.f32.bf16.bf16.f32 "
        "{%0,%1,%2,%3}, {%4,%5,%6,%7}, {%8,%9}, {%0,%1,%2,%3};"
        : "+f"(c[0]), "+f"(c[1]), "+f"(c[2]), "+f"(c[3])
        : "r"(a[0]), "r"(a[1]), "r"(a[2]), "r"(a[3]), "r"(b0), "r"(b1));
}

// pack 4 floats -> (hi u64, lo u64) bf16 split
__device__ __forceinline__ void split4(const float* x, u64& hi, u64& lo) {
    __nv_bfloat16 h[4]; float r[4];
    #pragma unroll
    for (int j = 0; j < 4; j++) { h[j] = __float2bfloat16_rn(x[j]); r[j] = x[j] - __bfloat162float(h[j]); }
    __nv_bfloat162 h01 = __nv_bfloat162(h[0], h[1]);
    __nv_bfloat162 h23 = __nv_bfloat162(h[2], h[3]);
    __nv_bfloat162 l01 = __floats2bfloat162_rn(r[0], r[1]);
    __nv_bfloat162 l23 = __floats2bfloat162_rn(r[2], r[3]);
    hi = (u64)*(uint32_t*)&h01 | ((u64)*(uint32_t*)&h23 << 32);
    lo = (u64)*(uint32_t*)&l01 | ((u64)*(uint32_t*)&l23 << 32);
}

// ---------------------------------------------------------------------------
// One CTA per (b,n). 256 threads, 2 CTAs/SM.
// ---------------------------------------------------------------------------
__global__ void __launch_bounds__(256, 2) colbert_mma(
    const float* __restrict__ qreps, const float* __restrict__ dreps,
    const int* __restrict__ dmask, const float* __restrict__ labels,
    float* __restrict__ out)
{
    extern __shared__ char smem[];
    const uint32_t sbase = smem_u32(smem);
    int*   msk  = (int*)(smem + S_MSK);
    float* part = (float*)(smem + S_PART);
    float* ws   = (float*)(smem + S_WS);

    const int bn   = blockIdx.x;       // b*16 + n
    const int b    = bn >> 4;
    const int t    = threadIdx.x;
    const int w    = t >> 5;
    const int lane = t & 31;

    // ---- q: normalize + bf16 hi/lo split into swizzled tiles ----
    #pragma unroll
    for (int i = 0; i < 8; i++) {
        int qrow = w + 8 * i;
        float4 v = *(const float4*)(qreps + ((size_t)(b * LQ + qrow)) * DD + lane * 4);
        float ss = v.x * v.x + v.y * v.y + v.z * v.z + v.w * v.w;
        #pragma unroll
        for (int o = 16; o; o >>= 1) ss += __shfl_xor_sync(0xFFFFFFFFu, ss, o);
        float rnq = 1.0f / fmaxf(sqrtf(ss), 1e-12f);
        float x[4] = {v.x * rnq, v.y * rnq, v.z * rnq, v.w * rnq};
        u64 hi, lo; split4(x, hi, lo);
        uint32_t byte = qrow * 256 + ((((lane >> 1) ^ (qrow & 7)) & 15) << 4) + ((lane & 1) << 3);
        *(u64*)(smem + S_QHI + byte) = hi;
        *(u64*)(smem + S_QLO + byte) = lo;
    }

    const float* dbase = dreps + (size_t)bn * LD * DD;
    const int*   mbase = dmask + bn * LD;

    // lane constants for ldmatrix addressing
    const int a_row   = w * 16 + (lane & 15);            // tok row for A frags
    const int a_cbadd = lane >> 4;
    const int b_rowp  = ((lane >> 4) & 1) * 8 + (lane & 7);  // row within q pair-tile
    const int b_cbadd = (lane >> 3) & 1;

    float m[16];
    #pragma unroll
    for (int i = 0; i < 16; i++) m[i] = -INFINITY;

    for (int c = 0; c < 2; c++) {
        __syncthreads();   // previous chunk's tiles/mask fully consumed

        // ---- load d chunk, normalize (+mask zero), split into tiles ----
        #pragma unroll
        for (int i = 0; i < 16; i++) {
            int tok = w + 8 * i;
            float4 v = *(const float4*)(dbase + ((size_t)(c * 128 + tok)) * DD + lane * 4);
            float ss = v.x * v.x + v.y * v.y + v.z * v.z + v.w * v.w;
            #pragma unroll
            for (int o = 16; o; o >>= 1) ss += __shfl_xor_sync(0xFFFFFFFFu, ss, o);
            int mk = (lane == 0) ? mbase[c * 128 + tok] : 0;
            mk = __shfl_sync(0xFFFFFFFFu, mk, 0);
            float sc = mk ? (1.0f / fmaxf(sqrtf(ss), 1e-12f)) : 0.0f;
            if (lane == 0) msk[tok] = mk;
            float x[4] = {v.x * sc, v.y * sc, v.z * sc, v.w * sc};
            u64 hi, lo; split4(x, hi, lo);
            uint32_t byte = tok * 256 + ((((lane >> 1) ^ (tok & 7)) & 15) << 4) + ((lane & 1) << 3);
            *(u64*)(smem + S_DHI + byte) = hi;
            *(u64*)(smem + S_DLO + byte) = lo;
        }
        __syncthreads();

        // ---- mainloop: 8 k-steps, 3-term bf16 split, 8 n-tiles ----
        float acc[8][4];
        #pragma unroll
        for (int nt = 0; nt < 8; nt++)
            #pragma unroll
            for (int j = 0; j < 4; j++) acc[nt][j] = 0.0f;

        #pragma unroll
        for (int ks = 0; ks < 8; ks++) {
            uint32_t ahi[4], alo[4];
            {
                int cb = ((2 * ks + a_cbadd) ^ (a_row & 7)) & 15;
                uint32_t addr = a_row * 256 + (cb << 4);
                ldsm4(ahi, sbase + S_DHI + addr);
                ldsm4(alo, sbase + S_DLO + addr);
            }
            #pragma unroll
            for (int p = 0; p < 4; p++) {
                int qrow = p * 16 + b_rowp;
                int cb = ((2 * ks + b_cbadd) ^ (qrow & 7)) & 15;
                uint32_t addr = qrow * 256 + (cb << 4);
                uint32_t bhi[4], blo[4];
                ldsm4(bhi, sbase + S_QHI + addr);
                ldsm4(blo, sbase + S_QLO + addr);
                // n-tile 2p  : {r0, r1},  n-tile 2p+1 : {r2, r3}
                mma_bf16(acc[2 * p],     ahi, bhi[0], bhi[1]);
                mma_bf16(acc[2 * p],     ahi, blo[0], blo[1]);
                mma_bf16(acc[2 * p],     alo, bhi[0], bhi[1]);
                mma_bf16(acc[2 * p + 1], ahi, bhi[2], bhi[3]);
                mma_bf16(acc[2 * p + 1], ahi, blo[2], blo[3]);
                mma_bf16(acc[2 * p + 1], alo, bhi[2], bhi[3]);
            }
        }

        // ---- epilogue: mask -> NEG, fold rows into per-lane q-col max ----
        {
            int r0 = w * 16 + (lane >> 2);
            bool on0 = (msk[r0] != 0);
            bool on1 = (msk[r0 + 8] != 0);
            #pragma unroll
            for (int nt = 0; nt < 8; nt++) {
                float v0 = fmaxf(on0 ? acc[nt][0] : NEGV, on1 ? acc[nt][2] : NEGV);
                float v1 = fmaxf(on0 ? acc[nt][1] : NEGV, on1 ? acc[nt][3] : NEGV);
                m[2 * nt]     = fmaxf(m[2 * nt],     v0);
                m[2 * nt + 1] = fmaxf(m[2 * nt + 1], v1);
            }
        }
    }

    // ---- lane reduce: max over lanes sharing the same q column ----
    #pragma unroll
    for (int i = 0; i < 16; i++) {
        float v = m[i];
        v = fmaxf(v, __shfl_xor_sync(0xFFFFFFFFu, v, 4));
        v = fmaxf(v, __shfl_xor_sync(0xFFFFFFFFu, v, 8));
        v = fmaxf(v, __shfl_xor_sync(0xFFFFFFFFu, v, 16));
        m[i] = v;
    }
    if (lane < 4) {
        #pragma unroll
        for (int nt = 0; nt < 8; nt++) {
            part[w * 64 + nt * 8 + lane * 2 + 0] = m[2 * nt];
            part[w * 64 + nt * 8 + lane * 2 + 1] = m[2 * nt + 1];
        }
    }
    __syncthreads();

    // ---- cross-warp max over toks, then sum over q ----
    if (t < 64) {
        float v = part[t];
        #pragma unroll
        for (int w2 = 1; w2 < 8; w2++) v = fmaxf(v, part[w2 * 64 + t]);
        #pragma unroll
        for (int o = 16; o; o >>= 1) v += __shfl_xor_sync(0xFFFFFFFFu, v, o);
        if (lane == 0) ws[t >> 5] = v;
    }
    __syncthreads();

    __shared__ int is_last;
    if (t == 0) {
        g_scores[bn] = ws[0] + ws[1];
        __threadfence();
        is_last = (atomicAdd(&g_cnt, 1) == (BB * NWAY - 1)) ? 1 : 0;
    }
    __syncthreads();

    // ---- last CTA: softmax over nway + KL (batchmean, log_target) ----
    if (is_last) {
        __threadfence();
        if (t < 32) {
            int bb = t;
            float s[NWAY];
            float mx = -INFINITY;
            #pragma unroll
            for (int n = 0; n < NWAY; n++) {
                s[n] = g_scores[bb * NWAY + n];
                mx = fmaxf(mx, s[n]);
            }
            float se = 0.0f;
            #pragma unroll
            for (int n = 0; n < NWAY; n++) se += expf(s[n] - mx);
            float lse = mx + logf(se);
            float loss = 0.0f;
            #pragma unroll
            for (int n = 0; n < NWAY; n++) {
                float lab = labels[bb * NWAY + n];
                loss += expf(lab) * (lab - (s[n] - lse));
            }
            #pragma unroll
            for (int o = 16; o; o >>= 1) loss += __shfl_xor_sync(0xFFFFFFFFu, loss, o);
            if (t == 0) {
                out[0] = loss / (float)BB;
                g_cnt = 0;    // reset for next graph replay
            }
        }
    }
}

// ---------------------------------------------------------------------------
extern "C" void kernel_launch(void* const* d_in, const int* in_sizes, int n_in,
                              void* d_out, int out_size) {
    (void)in_sizes; (void)n_in; (void)out_size;
    const float* q      = (const float*)d_in[0];
    const float* dreps  = (const float*)d_in[1];
    const int*   dmask  = (const int*)  d_in[2];
    const float* labels = (const float*)d_in[3];

    cudaFuncSetAttribute(colbert_mma, cudaFuncAttributeMaxDynamicSharedMemorySize, S_TOTAL);
    colbert_mma<<<BB * NWAY, 256, S_TOTAL>>>(q, dreps, dmask, labels, (float*)d_out);
}

// round 7
// speedup vs baseline: 2.5542x; 1.3330x over previous
#include <cuda_runtime.h>
#include <cuda_bf16.h>
#include <math.h>
#include <stdint.h>

#define BB   32
#define NWAY 16
#define LQ   64
#define LD   256
#define DD   128
#define NEGV (-9999.0f)

typedef unsigned long long u64;

__device__ float g_scores[BB * NWAY];
__device__ int   g_cnt;                 // zero-init; reset by last CTA each launch

// ---------------- smem layout (dynamic) ----------------
// Tiles: 256B rows (16 x 16B units), unit swizzle: u' = u ^ (row & 7)
#define S_PART  0                       // 8*64 floats = 2048
#define S_WS    2048                    // 2 floats
#define S_QHI   4096                    // 64 x 256B  = 16384
#define S_QLO   20480
#define S_DHI   36864                   // 128 x 256B = 32768 (warp-exclusive 16-row strips)
#define S_DLO   69632
#define S_TOTAL 102400

__device__ __forceinline__ uint32_t smem_u32(const void* p) {
    uint32_t a;
    asm("{ .reg .u64 t; cvta.to.shared.u64 t, %1; cvt.u32.u64 %0, t; }" : "=r"(a) : "l"(p));
    return a;
}

__device__ __forceinline__ void ldsm4(uint32_t* r, uint32_t addr) {
    asm volatile("ldmatrix.sync.aligned.m8n8.x4.shared.b16 {%0,%1,%2,%3}, [%4];"
                 : "=r"(r[0]), "=r"(r[1]), "=r"(r[2]), "=r"(r[3]) : "r"(addr));
}

__device__ __forceinline__ void mma_bf16(float* c, const uint32_t* a, uint32_t b0, uint32_t b1) {
    asm volatile(
        "mma.sync.aligned.m16n8k16.row.col.f32.bf16.bf16.f32 "
        "{%0,%1,%2,%3}, {%4,%5,%6,%7}, {%8,%9}, {%0,%1,%2,%3};"
        : "+f"(c[0]), "+f"(c[1]), "+f"(c[2]), "+f"(c[3])
        : "r"(a[0]), "r"(a[1]), "r"(a[2]), "r"(a[3]), "r"(b0), "r"(b1));
}

// pack 4 floats -> (hi u64, lo u64) bf16 split
__device__ __forceinline__ void split4(const float* x, u64& hi, u64& lo) {
    __nv_bfloat16 h[4]; float r[4];
    #pragma unroll
    for (int j = 0; j < 4; j++) { h[j] = __float2bfloat16_rn(x[j]); r[j] = x[j] - __bfloat162float(h[j]); }
    __nv_bfloat162 h01 = __nv_bfloat162(h[0], h[1]);
    __nv_bfloat162 h23 = __nv_bfloat162(h[2], h[3]);
    __nv_bfloat162 l01 = __floats2bfloat162_rn(r[0], r[1]);
    __nv_bfloat162 l23 = __floats2bfloat162_rn(r[2], r[3]);
    hi = (u64)*(uint32_t*)&h01 | ((u64)*(uint32_t*)&h23 << 32);
    lo = (u64)*(uint32_t*)&l01 | ((u64)*(uint32_t*)&l23 << 32);
}

// ---------------------------------------------------------------------------
// One CTA per (b,n). 256 threads, 2 CTAs/SM.
// ---------------------------------------------------------------------------
__global__ void __launch_bounds__(256, 2) colbert_mma(
    const float* __restrict__ qreps, const float* __restrict__ dreps,
    const int* __restrict__ dmask, const float* __restrict__ labels,
    float* __restrict__ out)
{
    extern __shared__ char smem[];
    const uint32_t sbase = smem_u32(smem);
    float* part = (float*)(smem + S_PART);
    float* ws   = (float*)(smem + S_WS);

    const int bn   = blockIdx.x;       // b*16 + n
    const int b    = bn >> 4;
    const int t    = threadIdx.x;
    const int w    = t >> 5;
    const int lane = t & 31;

    // ---- q: normalize + bf16 hi/lo split into swizzled tiles (shared) ----
    {
        float4 v[8];
        #pragma unroll
        for (int i = 0; i < 8; i++)
            v[i] = *(const float4*)(qreps + ((size_t)(b * LQ + w + 8 * i)) * DD + lane * 4);
        #pragma unroll
        for (int i = 0; i < 8; i++) {
            int qrow = w + 8 * i;
            float ss = v[i].x * v[i].x + v[i].y * v[i].y + v[i].z * v[i].z + v[i].w * v[i].w;
            #pragma unroll
            for (int o = 16; o; o >>= 1) ss += __shfl_xor_sync(0xFFFFFFFFu, ss, o);
            float rnq = rsqrtf(fmaxf(ss, 1e-24f));
            float x[4] = {v[i].x * rnq, v[i].y * rnq, v[i].z * rnq, v[i].w * rnq};
            u64 hi, lo; split4(x, hi, lo);
            uint32_t byte = qrow * 256 + ((((lane >> 1) ^ (qrow & 7)) & 15) << 4) + ((lane & 1) << 3);
            *(u64*)(smem + S_QHI + byte) = hi;
            *(u64*)(smem + S_QLO + byte) = lo;
        }
    }
    __syncthreads();   // Q tiles visible to all warps; the ONLY barrier before the end

    const float* dbase = dreps + (size_t)bn * LD * DD;
    const int*   mbase = dmask + bn * LD;

    // lane constants for ldmatrix addressing
    const int a_row   = w * 16 + (lane & 15);                // warp-exclusive rows
    const int a_cbadd = lane >> 4;
    const int b_rowp  = ((lane >> 4) & 1) * 8 + (lane & 7);
    const int b_cbadd = (lane >> 3) & 1;

    float m[16];
    #pragma unroll
    for (int i = 0; i < 16; i++) m[i] = -INFINITY;

    for (int c = 0; c < 2; c++) {
        // ---- warp-private: load 16 toks, normalize (+mask zero), split ----
        int mymk = (lane < 16) ? mbase[c * 128 + w * 16 + lane] : 0;
        unsigned mbits = __ballot_sync(0xFFFFFFFFu, mymk != 0) & 0xFFFFu;

        #pragma unroll
        for (int batch = 0; batch < 2; batch++) {
            float4 v[8];
            #pragma unroll
            for (int j = 0; j < 8; j++) {
                int tok = w * 16 + batch * 8 + j;
                v[j] = *(const float4*)(dbase + ((size_t)(c * 128 + tok)) * DD + lane * 4);
            }
            #pragma unroll
            for (int j = 0; j < 8; j++) {
                int tok = w * 16 + batch * 8 + j;
                float ss = v[j].x * v[j].x + v[j].y * v[j].y + v[j].z * v[j].z + v[j].w * v[j].w;
                #pragma unroll
                for (int o = 16; o; o >>= 1) ss += __shfl_xor_sync(0xFFFFFFFFu, ss, o);
                float sc = ((mbits >> (batch * 8 + j)) & 1) ? rsqrtf(fmaxf(ss, 1e-24f)) : 0.0f;
                float x[4] = {v[j].x * sc, v[j].y * sc, v[j].z * sc, v[j].w * sc};
                u64 hi, lo; split4(x, hi, lo);
                uint32_t byte = tok * 256 + ((((lane >> 1) ^ (tok & 7)) & 15) << 4) + ((lane & 1) << 3);
                *(u64*)(smem + S_DHI + byte) = hi;
                *(u64*)(smem + S_DLO + byte) = lo;
            }
        }
        __syncwarp();   // warp-exclusive tile strip: warp-level sync suffices

        // ---- mainloop: 8 k-steps, 3-term bf16 split, 8 n-tiles ----
        float acc[8][4];
        #pragma unroll
        for (int nt = 0; nt < 8; nt++)
            #pragma unroll
            for (int j = 0; j < 4; j++) acc[nt][j] = 0.0f;

        #pragma unroll
        for (int ks = 0; ks < 8; ks++) {
            uint32_t ahi[4], alo[4];
            {
                int cb = ((2 * ks + a_cbadd) ^ (a_row & 7)) & 15;
                uint32_t addr = a_row * 256 + (cb << 4);
                ldsm4(ahi, sbase + S_DHI + addr);
                ldsm4(alo, sbase + S_DLO + addr);
            }
            #pragma unroll
            for (int p = 0; p < 4; p++) {
                int qrow = p * 16 + b_rowp;
                int cb = ((2 * ks + b_cbadd) ^ (qrow & 7)) & 15;
                uint32_t addr = qrow * 256 + (cb << 4);
                uint32_t bhi[4], blo[4];
                ldsm4(bhi, sbase + S_QHI + addr);
                ldsm4(blo, sbase + S_QLO + addr);
                mma_bf16(acc[2 * p],     ahi, bhi[0], bhi[1]);
                mma_bf16(acc[2 * p],     ahi, blo[0], blo[1]);
                mma_bf16(acc[2 * p],     alo, bhi[0], bhi[1]);
                mma_bf16(acc[2 * p + 1], ahi, bhi[2], bhi[3]);
                mma_bf16(acc[2 * p + 1], ahi, blo[2], blo[3]);
                mma_bf16(acc[2 * p + 1], alo, bhi[2], bhi[3]);
            }
        }
        __syncwarp();   // all LDSM reads done before next chunk overwrites strip

        // ---- epilogue: mask -> NEG, fold rows into per-lane q-col max ----
        {
            int rl = lane >> 2;
            bool on0 = (mbits >> rl) & 1;
            bool on1 = (mbits >> (rl + 8)) & 1;
            #pragma unroll
            for (int nt = 0; nt < 8; nt++) {
                float v0 = fmaxf(on0 ? acc[nt][0] : NEGV, on1 ? acc[nt][2] : NEGV);
                float v1 = fmaxf(on0 ? acc[nt][1] : NEGV, on1 ? acc[nt][3] : NEGV);
                m[2 * nt]     = fmaxf(m[2 * nt],     v0);
                m[2 * nt + 1] = fmaxf(m[2 * nt + 1], v1);
            }
        }
    }

    // ---- lane reduce: max over lanes sharing the same q column ----
    #pragma unroll
    for (int i = 0; i < 16; i++) {
        float v = m[i];
        v = fmaxf(v, __shfl_xor_sync(0xFFFFFFFFu, v, 4));
        v = fmaxf(v, __shfl_xor_sync(0xFFFFFFFFu, v, 8));
        v = fmaxf(v, __shfl_xor_sync(0xFFFFFFFFu, v, 16));
        m[i] = v;
    }
    if (lane < 4) {
        #pragma unroll
        for (int nt = 0; nt < 8; nt++) {
            part[w * 64 + nt * 8 + lane * 2 + 0] = m[2 * nt];
            part[w * 64 + nt * 8 + lane * 2 + 1] = m[2 * nt + 1];
        }
    }
    __syncthreads();

    // ---- cross-warp max over toks, then sum over q ----
    if (t < 64) {
        float v = part[t];
        #pragma unroll
        for (int w2 = 1; w2 < 8; w2++) v = fmaxf(v, part[w2 * 64 + t]);
        #pragma unroll
        for (int o = 16; o; o >>= 1) v += __shfl_xor_sync(0xFFFFFFFFu, v, o);
        if (lane == 0) ws[t >> 5] = v;
    }
    __syncthreads();

    __shared__ int is_last;
    if (t == 0) {
        g_scores[bn] = ws[0] + ws[1];
        __threadfence();
        is_last = (atomicAdd(&g_cnt, 1) == (BB * NWAY - 1)) ? 1 : 0;
    }
    __syncthreads();

    // ---- last CTA: softmax over nway + KL (batchmean, log_target) ----
    if (is_last) {
        __threadfence();
        if (t < 32) {
            int bb = t;
            float s[NWAY];
            float mx = -INFINITY;
            #pragma unroll
            for (int n = 0; n < NWAY; n++) {
                s[n] = g_scores[bb * NWAY + n];
                mx = fmaxf(mx, s[n]);
            }
            float se = 0.0f;
            #pragma unroll
            for (int n = 0; n < NWAY; n++) se += expf(s[n] - mx);
            float lse = mx + logf(se);
            float loss = 0.0f;
            #pragma unroll
            for (int n = 0; n < NWAY; n++) {
                float lab = labels[bb * NWAY + n];
                loss += expf(lab) * (lab - (s[n] - lse));
            }
            #pragma unroll
            for (int o = 16; o; o >>= 1) loss += __shfl_xor_sync(0xFFFFFFFFu, loss, o);
            if (t == 0) {
                out[0] = loss / (float)BB;
                g_cnt = 0;    // reset for next graph replay
            }
        }
    }
}

// ---------------------------------------------------------------------------
extern "C" void kernel_launch(void* const* d_in, const int* in_sizes, int n_in,
                              void* d_out, int out_size) {
    (void)in_sizes; (void)n_in; (void)out_size;
    const float* q      = (const float*)d_in[0];
    const float* dreps  = (const float*)d_in[1];
    const int*   dmask  = (const int*)  d_in[2];
    const float* labels = (const float*)d_in[3];

    cudaFuncSetAttribute(colbert_mma, cudaFuncAttributeMaxDynamicSharedMemorySize, S_TOTAL);
    colbert_mma<<<BB * NWAY, 256, S_TOTAL>>>(q, dreps, dmask, labels, (float*)d_out);
}

// round 8
// speedup vs baseline: 2.9778x; 1.1658x over previous
#include <cuda_runtime.h>
#include <cuda_fp16.h>
#include <math.h>
#include <stdint.h>

#define BB   32
#define NWAY 16
#define LQ   64
#define LD   256
#define DD   128
#define NEGV (-9999.0f)

typedef unsigned long long u64;

__device__ float g_scores[BB * NWAY];
__device__ int   g_cnt;                 // zero-init; reset by last CTA each launch

// ---------------- smem layout (dynamic) ----------------
// Tiles: 256B rows (16 x 16B units), unit swizzle: u' = u ^ (row & 7)
#define S_PART  0                       // 8*64 floats = 2048
#define S_WS    2048                    // 2 floats
#define S_QHI   4096                    // 64 x 256B  = 16384
#define S_QLO   20480
#define S_DH    36864                   // 128 x 256B = 32768 (warp-exclusive strips)
#define S_TOTAL 69632

__device__ __forceinline__ uint32_t smem_u32(const void* p) {
    uint32_t a;
    asm("{ .reg .u64 t; cvta.to.shared.u64 t, %1; cvt.u32.u64 %0, t; }" : "=r"(a) : "l"(p));
    return a;
}

__device__ __forceinline__ void ldsm4(uint32_t* r, uint32_t addr) {
    asm volatile("ldmatrix.sync.aligned.m8n8.x4.shared.b16 {%0,%1,%2,%3}, [%4];"
                 : "=r"(r[0]), "=r"(r[1]), "=r"(r[2]), "=r"(r[3]) : "r"(addr));
}

__device__ __forceinline__ void mma_f16(float* c, const uint32_t* a, uint32_t b0, uint32_t b1) {
    asm volatile(
        "mma.sync.aligned.m16n8k16.row.col.f32.f16.f16.f32 "
        "{%0,%1,%2,%3}, {%4,%5,%6,%7}, {%8,%9}, {%0,%1,%2,%3};"
        : "+f"(c[0]), "+f"(c[1]), "+f"(c[2]), "+f"(c[3])
        : "r"(a[0]), "r"(a[1]), "r"(a[2]), "r"(a[3]), "r"(b0), "r"(b1));
}

// float4 -> 4 fp16 (rounded), packed in u64
__device__ __forceinline__ u64 cvt4h(float4 v) {
    __half2 a = __floats2half2_rn(v.x, v.y);
    __half2 b = __floats2half2_rn(v.z, v.w);
    return (u64)*(uint32_t*)&a | ((u64)*(uint32_t*)&b << 32);
}

// float4 -> fp16 hi/lo split (q operand: near-exact 2-term)
__device__ __forceinline__ void split4h(float4 v, u64& hi, u64& lo) {
    __half2 a = __floats2half2_rn(v.x, v.y);
    __half2 b = __floats2half2_rn(v.z, v.w);
    float2 fa = __half22float2(a), fb = __half22float2(b);
    __half2 la = __floats2half2_rn(v.x - fa.x, v.y - fa.y);
    __half2 lb = __floats2half2_rn(v.z - fb.x, v.w - fb.y);
    hi = (u64)*(uint32_t*)&a  | ((u64)*(uint32_t*)&b  << 32);
    lo = (u64)*(uint32_t*)&la | ((u64)*(uint32_t*)&lb << 32);
}

// ---------------------------------------------------------------------------
// One CTA per (b,n). 256 threads, 2 CTAs/SM.
// ---------------------------------------------------------------------------
__global__ void __launch_bounds__(256, 2) colbert_mma(
    const float* __restrict__ qreps, const float* __restrict__ dreps,
    const int* __restrict__ dmask, const float* __restrict__ labels,
    float* __restrict__ out)
{
    extern __shared__ char smem[];
    const uint32_t sbase = smem_u32(smem);
    float* part = (float*)(smem + S_PART);
    float* ws   = (float*)(smem + S_WS);

    const int bn   = blockIdx.x;       // b*16 + n
    const int b    = bn >> 4;
    const int t    = threadIdx.x;
    const int w    = t >> 5;
    const int lane = t & 31;

    // ---- q: normalize + fp16 hi/lo split into swizzled tiles (shared) ----
    {
        float4 v[8];
        #pragma unroll
        for (int i = 0; i < 8; i++)
            v[i] = *(const float4*)(qreps + ((size_t)(b * LQ + w + 8 * i)) * DD + lane * 4);
        #pragma unroll
        for (int i = 0; i < 8; i++) {
            int qrow = w + 8 * i;
            float ss = v[i].x * v[i].x + v[i].y * v[i].y + v[i].z * v[i].z + v[i].w * v[i].w;
            #pragma unroll
            for (int o = 16; o; o >>= 1) ss += __shfl_xor_sync(0xFFFFFFFFu, ss, o);
            float rnq = rsqrtf(fmaxf(ss, 1e-24f));
            float4 x = make_float4(v[i].x * rnq, v[i].y * rnq, v[i].z * rnq, v[i].w * rnq);
            u64 hi, lo; split4h(x, hi, lo);
            uint32_t byte = qrow * 256 + ((((lane >> 1) ^ (qrow & 7)) & 15) << 4) + ((lane & 1) << 3);
            *(u64*)(smem + S_QHI + byte) = hi;
            *(u64*)(smem + S_QLO + byte) = lo;
        }
    }
    __syncthreads();   // Q tiles visible to all warps; the ONLY barrier before the end

    const float* dbase = dreps + (size_t)bn * LD * DD;
    const int*   mbase = dmask + bn * LD;

    // lane constants for ldmatrix addressing
    const int a_row   = w * 16 + (lane & 15);                // warp-exclusive rows
    const int a_cbadd = lane >> 4;
    const int b_rowp  = ((lane >> 4) & 1) * 8 + (lane & 7);
    const int b_cbadd = (lane >> 3) & 1;

    float m[16];
    #pragma unroll
    for (int i = 0; i < 16; i++) m[i] = -INFINITY;

    for (int c = 0; c < 2; c++) {
        // ---- warp-private: load 16 toks, normalize (+mask zero), cvt fp16 ----
        int mymk = (lane < 16) ? mbase[c * 128 + w * 16 + lane] : 0;
        unsigned mbits = __ballot_sync(0xFFFFFFFFu, mymk != 0) & 0xFFFFu;

        #pragma unroll
        for (int batch = 0; batch < 2; batch++) {
            float4 v[8];
            #pragma unroll
            for (int j = 0; j < 8; j++) {
                int tok = w * 16 + batch * 8 + j;
                v[j] = *(const float4*)(dbase + ((size_t)(c * 128 + tok)) * DD + lane * 4);
            }
            #pragma unroll
            for (int j = 0; j < 8; j++) {
                int tok = w * 16 + batch * 8 + j;
                float ss = v[j].x * v[j].x + v[j].y * v[j].y + v[j].z * v[j].z + v[j].w * v[j].w;
                #pragma unroll
                for (int o = 16; o; o >>= 1) ss += __shfl_xor_sync(0xFFFFFFFFu, ss, o);
                float sc = ((mbits >> (batch * 8 + j)) & 1) ? rsqrtf(fmaxf(ss, 1e-24f)) : 0.0f;
                float4 x = make_float4(v[j].x * sc, v[j].y * sc, v[j].z * sc, v[j].w * sc);
                u64 hv = cvt4h(x);
                uint32_t byte = tok * 256 + ((((lane >> 1) ^ (tok & 7)) & 15) << 4) + ((lane & 1) << 3);
                *(u64*)(smem + S_DH + byte) = hv;
            }
        }
        __syncwarp();   // warp-exclusive tile strip: warp-level sync suffices

        // ---- mainloop: 8 k-steps, 2-term fp16 (d single, q hi+lo), 8 n-tiles ----
        float acc[8][4];
        #pragma unroll
        for (int nt = 0; nt < 8; nt++)
            #pragma unroll
            for (int j = 0; j < 4; j++) acc[nt][j] = 0.0f;

        #pragma unroll
        for (int ks = 0; ks < 8; ks++) {
            uint32_t ah[4];
            {
                int cb = ((2 * ks + a_cbadd) ^ (a_row & 7)) & 15;
                ldsm4(ah, sbase + S_DH + a_row * 256 + (cb << 4));
            }
            #pragma unroll
            for (int p = 0; p < 4; p++) {
                int qrow = p * 16 + b_rowp;
                int cb = ((2 * ks + b_cbadd) ^ (qrow & 7)) & 15;
                uint32_t addr = qrow * 256 + (cb << 4);
                uint32_t bhi[4], blo[4];
                ldsm4(bhi, sbase + S_QHI + addr);
                ldsm4(blo, sbase + S_QLO + addr);
                mma_f16(acc[2 * p],     ah, bhi[0], bhi[1]);
                mma_f16(acc[2 * p],     ah, blo[0], blo[1]);
                mma_f16(acc[2 * p + 1], ah, bhi[2], bhi[3]);
                mma_f16(acc[2 * p + 1], ah, blo[2], blo[3]);
            }
        }
        __syncwarp();   // all LDSM reads done before next chunk overwrites strip

        // ---- epilogue: mask -> NEG, fold rows into per-lane q-col max ----
        {
            int rl = lane >> 2;
            bool on0 = (mbits >> rl) & 1;
            bool on1 = (mbits >> (rl + 8)) & 1;
            #pragma unroll
            for (int nt = 0; nt < 8; nt++) {
                float v0 = fmaxf(on0 ? acc[nt][0] : NEGV, on1 ? acc[nt][2] : NEGV);
                float v1 = fmaxf(on0 ? acc[nt][1] : NEGV, on1 ? acc[nt][3] : NEGV);
                m[2 * nt]     = fmaxf(m[2 * nt],     v0);
                m[2 * nt + 1] = fmaxf(m[2 * nt + 1], v1);
            }
        }
    }

    // ---- lane reduce: max over lanes sharing the same q column ----
    #pragma unroll
    for (int i = 0; i < 16; i++) {
        float v = m[i];
        v = fmaxf(v, __shfl_xor_sync(0xFFFFFFFFu, v, 4));
        v = fmaxf(v, __shfl_xor_sync(0xFFFFFFFFu, v, 8));
        v = fmaxf(v, __shfl_xor_sync(0xFFFFFFFFu, v, 16));
        m[i] = v;
    }
    if (lane < 4) {
        #pragma unroll
        for (int nt = 0; nt < 8; nt++) {
            part[w * 64 + nt * 8 + lane * 2 + 0] = m[2 * nt];
            part[w * 64 + nt * 8 + lane * 2 + 1] = m[2 * nt + 1];
        }
    }
    __syncthreads();

    // ---- cross-warp max over toks, then sum over q ----
    if (t < 64) {
        float v = part[t];
        #pragma unroll
        for (int w2 = 1; w2 < 8; w2++) v = fmaxf(v, part[w2 * 64 + t]);
        #pragma unroll
        for (int o = 16; o; o >>= 1) v += __shfl_xor_sync(0xFFFFFFFFu, v, o);
        if (lane == 0) ws[t >> 5] = v;
    }
    __syncthreads();

    __shared__ int is_last;
    if (t == 0) {
        g_scores[bn] = ws[0] + ws[1];
        __threadfence();
        is_last = (atomicAdd(&g_cnt, 1) == (BB * NWAY - 1)) ? 1 : 0;
    }
    __syncthreads();

    // ---- last CTA: softmax over nway + KL (batchmean, log_target) ----
    if (is_last) {
        __threadfence();
        if (t < 32) {
            int bb = t;
            float s[NWAY];
            float mx = -INFINITY;
            #pragma unroll
            for (int n = 0; n < NWAY; n++) {
                s[n] = g_scores[bb * NWAY + n];
                mx = fmaxf(mx, s[n]);
            }
            float se = 0.0f;
            #pragma unroll
            for (int n = 0; n < NWAY; n++) se += expf(s[n] - mx);
            float lse = mx + logf(se);
            float loss = 0.0f;
            #pragma unroll
            for (int n = 0; n < NWAY; n++) {
                float lab = labels[bb * NWAY + n];
                loss += expf(lab) * (lab - (s[n] - lse));
            }
            #pragma unroll
            for (int o = 16; o; o >>= 1) loss += __shfl_xor_sync(0xFFFFFFFFu, loss, o);
            if (t == 0) {
                out[0] = loss / (float)BB;
                g_cnt = 0;    // reset for next graph replay
            }
        }
    }
}

// ---------------------------------------------------------------------------
extern "C" void kernel_launch(void* const* d_in, const int* in_sizes, int n_in,
                              void* d_out, int out_size) {
    (void)in_sizes; (void)n_in; (void)out_size;
    const float* q      = (const float*)d_in[0];
    const float* dreps  = (const float*)d_in[1];
    const int*   dmask  = (const int*)  d_in[2];
    const float* labels = (const float*)d_in[3];

    cudaFuncSetAttribute(colbert_mma, cudaFuncAttributeMaxDynamicSharedMemorySize, S_TOTAL);
    colbert_mma<<<BB * NWAY, 256, S_TOTAL>>>(q, dreps, dmask, labels, (float*)d_out);
}